// round 10
// baseline (speedup 1.0000x reference)
#include <cuda_runtime.h>
#include <cuda_bf16.h>
#include <cstdint>

#define Nn 100000
#define Ee 600000

// ---------------- scratch (allocation-free: __device__ globals) --------------
__device__ float g_agg[Nn * 128];
__device__ float g_h[Nn * 128];
__device__ __align__(16) __nv_bfloat16 g_wb[6][2][128 * 136];
__device__ __align__(16) __nv_bfloat16 g_web[2][2][128 * 40];

// ---------------- helpers -----------------------------------------------------
__device__ __forceinline__ void red_add_v2(float* p, float2 v) {
    asm volatile("red.global.add.v2.f32 [%0], {%1, %2};"
                 :: "l"(p), "f"(v.x), "f"(v.y) : "memory");
}
__device__ __forceinline__ uint32_t smem_u32(const void* p) {
    return (uint32_t)__cvta_generic_to_shared(p);
}
__device__ __forceinline__ void cp_async16(uint32_t dst, const void* src) {
    asm volatile("cp.async.cg.shared.global [%0], [%1], 16;"
                 :: "r"(dst), "l"(src));
}
__device__ __forceinline__ void cp_commit() {
    asm volatile("cp.async.commit_group;");
}
__device__ __forceinline__ void cp_wait0() {
    asm volatile("cp.async.wait_group 0;" ::: "memory");
}
__device__ __forceinline__ void ldx4(uint32_t* r, uint32_t addr) {
    asm volatile("ldmatrix.sync.aligned.m8n8.x4.shared.b16 {%0, %1, %2, %3}, [%4];"
                 : "=r"(r[0]), "=r"(r[1]), "=r"(r[2]), "=r"(r[3]) : "r"(addr));
}
__device__ __forceinline__ void mma_bf16(float* c, const uint32_t* a,
                                         const uint32_t* b) {
    asm volatile("mma.sync.aligned.m16n8k16.row.col.f32.bf16.bf16.f32 "
                 "{%0, %1, %2, %3}, {%4, %5, %6, %7}, {%8, %9}, {%0, %1, %2, %3};"
                 : "+f"(c[0]), "+f"(c[1]), "+f"(c[2]), "+f"(c[3])
                 : "r"(a[0]), "r"(a[1]), "r"(a[2]), "r"(a[3]),
                   "r"(b[0]), "r"(b[1]));
}
__device__ __forceinline__ uint32_t bf2_u32(__nv_bfloat162 x) {
    uint32_t r;
    memcpy(&r, &x, 4);
    return r;
}
__device__ __forceinline__ uint32_t split_hi2(float a, float b, uint32_t& lo) {
    __nv_bfloat162 h = __floats2bfloat162_rn(a, b);
    __nv_bfloat162 l = __floats2bfloat162_rn(a - __bfloat162float(h.x),
                                             b - __bfloat162float(h.y));
    lo = bf2_u32(l);
    return bf2_u32(h);
}
// ---- bulk copy + mbarrier ----
__device__ __forceinline__ void mbar_init(uint32_t mb, uint32_t cnt) {
    asm volatile("mbarrier.init.shared.b64 [%0], %1;" :: "r"(mb), "r"(cnt) : "memory");
}
__device__ __forceinline__ void mbar_expect(uint32_t mb, uint32_t bytes) {
    asm volatile("mbarrier.arrive.expect_tx.shared.b64 _, [%0], %1;"
                 :: "r"(mb), "r"(bytes) : "memory");
}
__device__ __forceinline__ void bulk_ld(uint32_t dst, const void* src,
                                        uint32_t bytes, uint32_t mb) {
    asm volatile("cp.async.bulk.shared::cta.global.mbarrier::complete_tx::bytes "
                 "[%0], [%1], %2, [%3];"
                 :: "r"(dst), "l"(src), "r"(bytes), "r"(mb) : "memory");
}
__device__ __forceinline__ void mbar_wait(uint32_t mb, uint32_t parity) {
    uint32_t done;
    asm volatile("{\n\t.reg .pred p;\n\t"
                 "mbarrier.try_wait.parity.acquire.cta.shared::cta.b64 p, [%1], %2;\n\t"
                 "selp.b32 %0, 1, 0, p;\n\t}"
                 : "=r"(done) : "r"(mb), "r"(parity) : "memory");
    if (!done) {
        asm volatile("{\n\t.reg .pred P1;\n\t"
                     "WL_%=:\n\t"
                     "mbarrier.try_wait.parity.acquire.cta.shared::cta.b64 P1, [%0], %1, 0x989680;\n\t"
                     "@P1 bra.uni WD_%=;\n\t"
                     "bra.uni WL_%=;\n\t"
                     "WD_%=:\n\t}"
                     :: "r"(mb), "r"(parity) : "memory");
    }
}

// ---------------- zero kernel (write-only agg init) ----------------------------
__global__ void __launch_bounds__(256) zero_kernel(float4* __restrict__ dst, int n4) {
    int i = blockIdx.x * blockDim.x + threadIdx.x;
    if (i < n4) dst[i] = make_float4(0.f, 0.f, 0.f, 0.f);
}

// ---------------- fused weight prep (one launch) -------------------------------
__global__ void __launch_bounds__(256)
prep_all(const float* __restrict__ W1a, const float* __restrict__ W1b,
         const float* __restrict__ W2a, const float* __restrict__ W2b,
         const float* __restrict__ Wfc1, const float* __restrict__ Wfc2,
         const float* __restrict__ We1, const float* __restrict__ We2,
         __nv_bfloat16* __restrict__ wb, __nv_bfloat16* __restrict__ web) {
    int id = blockIdx.x * 256 + threadIdx.x;
    if (id < 81920) {
        int m = id / 16384, e = id % 16384;
        const float* W = (m == 0) ? W1a : (m == 1) ? W1b
                       : (m == 2) ? W2a : (m == 3) ? W2b : Wfc1;
        int n = e >> 7, k = e & 127;
        float v = W[k * 128 + n];
        __nv_bfloat16 h = __float2bfloat16_rn(v);
        __nv_bfloat16 l = __float2bfloat16_rn(v - __bfloat162float(h));
        wb[(size_t)m * 2 * 128 * 136 + n * 136 + k] = h;
        wb[((size_t)m * 2 + 1) * 128 * 136 + n * 136 + k] = l;
    } else if (id < 90112) {
        int e = id - 81920;
        int n = e >> 7, k = e & 127;
        float v = Wfc2[k * 64 + n];
        __nv_bfloat16 h = __float2bfloat16_rn(v);
        __nv_bfloat16 l = __float2bfloat16_rn(v - __bfloat162float(h));
        wb[(size_t)5 * 2 * 128 * 136 + n * 136 + k] = h;
        wb[((size_t)5 * 2 + 1) * 128 * 136 + n * 136 + k] = l;
    } else if (id < 98304) {
        int e = id - 90112;
        int m = e >> 12; e &= 4095;
        int n = e >> 5, k = e & 31;
        const float* We = m ? We2 : We1;
        float v = We[k * 128 + n];
        __nv_bfloat16 h = __float2bfloat16_rn(v);
        __nv_bfloat16 l = __float2bfloat16_rn(v - __bfloat162float(h));
        web[(size_t)m * 2 * 128 * 40 + n * 40 + k] = h;
        web[((size_t)m * 2 + 1) * 128 * 40 + n * 40 + k] = l;
    }
}

// ---------------- HMMA fused edge kernel (R8 form — best known) ---------------
__global__ void __launch_bounds__(256, 2)
edge_kernel(const float* __restrict__ xin,
            const int* __restrict__ src, const int* __restrict__ dst,
            const float* __restrict__ ef,
            const __nv_bfloat16* __restrict__ Weh,
            const __nv_bfloat16* __restrict__ Wel,
            const float* __restrict__ be,
            float* __restrict__ agg) {
    __shared__ __align__(16) __nv_bfloat16 sWeh[128 * 40], sWel[128 * 40];
    __shared__ __align__(16) __nv_bfloat16 sEfh[128 * 40], sEfl[128 * 40];
    __shared__ float sbias[128];
    __shared__ int ssrc[128], sdst[128];

    const int tid  = threadIdx.x;
    const int wid  = tid >> 5;
    const int lane = tid & 31;
    const int base = blockIdx.x * 128;
    const int nvalid = min(128, Ee - base);

    const uint32_t swh = smem_u32(sWeh), swl = smem_u32(sWel);
    for (int i = tid; i < 640; i += 256) {
        cp_async16(swh + i * 16, (const char*)Weh + i * 16);
        cp_async16(swl + i * 16, (const char*)Wel + i * 16);
    }
    cp_commit();

    if (tid < 128) {
        sbias[tid] = be[tid];
        int e = min(base + tid, Ee - 1);
        ssrc[tid] = src[e];
        sdst[tid] = dst[e];
    }

    {
        const int edge = tid >> 1, half = tid & 1;
        int ge = min(base + edge, Ee - 1);
        const float4* ap = (const float4*)(ef + (size_t)ge * 32 + half * 16);
        const uint32_t dh = smem_u32(sEfh) + edge * 80 + half * 32;
        const uint32_t dl = smem_u32(sEfl) + edge * 80 + half * 32;
#pragma unroll
        for (int i = 0; i < 4; i++) {
            float4 v = ap[i];
            uint32_t l0, l1;
            uint32_t h0 = split_hi2(v.x, v.y, l0);
            uint32_t h1 = split_hi2(v.z, v.w, l1);
            asm volatile("st.shared.v2.b32 [%0], {%1, %2};"
                         :: "r"(dh + i * 8), "r"(h0), "r"(h1));
            asm volatile("st.shared.v2.b32 [%0], {%1, %2};"
                         :: "r"(dl + i * 8), "r"(l0), "r"(l1));
        }
    }
    cp_wait0();
    __syncthreads();

    const int g = lane >> 2, tq = lane & 3;
    const uint32_t aoff = smem_u32(sEfh)
        + (uint32_t)(wid * 16 + (lane & 15)) * 80 + ((lane >> 4) ? 16 : 0);
    const uint32_t aloff = aoff + (smem_u32(sEfl) - smem_u32(sEfh));
    const int brow = (lane & 7) + ((lane >> 4) << 3);
    const uint32_t boff = smem_u32(sWeh) + (uint32_t)brow * 80 + ((lane & 8) ? 16 : 0);
    const uint32_t bloff = boff + (smem_u32(sWel) - smem_u32(sWeh));

    float acc[16][4];
#pragma unroll
    for (int ni = 0; ni < 16; ni++) {
        float2 b = *(const float2*)(sbias + ni * 8 + tq * 2);
        acc[ni][0] = b.x; acc[ni][1] = b.y;
        acc[ni][2] = b.x; acc[ni][3] = b.y;
    }

#pragma unroll
    for (int ks = 0; ks < 2; ks++) {
        uint32_t ah[4], al[4];
        ldx4(ah, aoff + ks * 32);
        ldx4(al, aloff + ks * 32);
#pragma unroll
        for (int np = 0; np < 8; np++) {
            uint32_t rh[4], rl[4];
            ldx4(rh, boff + np * (16 * 80) + ks * 32);
            ldx4(rl, bloff + np * (16 * 80) + ks * 32);
            uint32_t bh0[2] = {rh[0], rh[1]}, bh1[2] = {rh[2], rh[3]};
            uint32_t bl0[2] = {rl[0], rl[1]}, bl1[2] = {rl[2], rl[3]};
            mma_bf16(acc[np * 2],     ah, bh0);
            mma_bf16(acc[np * 2],     ah, bl0);
            mma_bf16(acc[np * 2],     al, bh0);
            mma_bf16(acc[np * 2 + 1], ah, bh1);
            mma_bf16(acc[np * 2 + 1], ah, bl1);
            mma_bf16(acc[np * 2 + 1], al, bh1);
        }
    }

    const int er0 = wid * 16 + g;
#pragma unroll
    for (int half = 0; half < 2; half++) {
        const int er = er0 + half * 8;
        if (er < nvalid) {
            const size_t srow = (size_t)ssrc[er] * 128;
            const size_t drow = (size_t)sdst[er] * 128;
#pragma unroll
            for (int ni = 0; ni < 16; ni++) {
                const int col = ni * 8 + tq * 2;
                float2 xv = *(const float2*)(xin + srow + col);
                float2 m;
                m.x = fmaxf(xv.x + acc[ni][half * 2 + 0], 0.f);
                m.y = fmaxf(xv.y + acc[ni][half * 2 + 1], 0.f);
                red_add_v2(agg + drow + col, m);
            }
        }
    }
}

// ---------------- multi-stage fused node GEMM ----------------------------------
// A = A1 + A2 (fp32), then NST chained GEMM stages with streamed W (one buffer,
// cp.async.bulk per stage), T overwriting the A smem buffer. 128 thr, M-tile 64,
// 2 CTAs/SM. Stage s act: acts[s] (1=relu, 2=tanh, 0=none). Last stage: COUTL
// cols to global.
template <int NF>
__device__ __forceinline__ void mma_stage(
    uint32_t sAh, uint32_t sAl, uint32_t sWh, uint32_t sWl,
    uint32_t aoff, int cw, int lane, const float* bias,
    float (&acc)[4][NF][4]) {
    const int tq = lane & 3;
    const int brow = (lane & 7) + ((lane >> 4) << 3);
    const uint32_t boff = (uint32_t)(cw * (8 * NF) + brow) * 272
                        + ((lane & 8) ? 16 : 0);
#pragma unroll
    for (int ni = 0; ni < NF; ni++) {
        float2 b = __ldg((const float2*)(bias + cw * (8 * NF) + ni * 8 + tq * 2));
#pragma unroll
        for (int mi = 0; mi < 4; mi++) {
            acc[mi][ni][0] = b.x; acc[mi][ni][1] = b.y;
            acc[mi][ni][2] = b.x; acc[mi][ni][3] = b.y;
        }
    }
#pragma unroll
    for (int ks = 0; ks < 8; ks++) {
        uint32_t ah[4][4], al[4][4], bh[NF][2], bl[NF][2];
#pragma unroll
        for (int mi = 0; mi < 4; mi++) {
            ldx4(ah[mi], sAh + aoff + mi * 4352 + ks * 32);
            ldx4(al[mi], sAl + aoff + mi * 4352 + ks * 32);
        }
#pragma unroll
        for (int np = 0; np < NF / 2; np++) {
            uint32_t r[4];
            ldx4(r, sWh + boff + np * 4352 + ks * 32);
            bh[np * 2][0] = r[0]; bh[np * 2][1] = r[1];
            bh[np * 2 + 1][0] = r[2]; bh[np * 2 + 1][1] = r[3];
            ldx4(r, sWl + boff + np * 4352 + ks * 32);
            bl[np * 2][0] = r[0]; bl[np * 2][1] = r[1];
            bl[np * 2 + 1][0] = r[2]; bl[np * 2 + 1][1] = r[3];
        }
#pragma unroll
        for (int mi = 0; mi < 4; mi++)
#pragma unroll
            for (int ni = 0; ni < NF; ni++) {
                mma_bf16(acc[mi][ni], ah[mi], bh[ni]);
                mma_bf16(acc[mi][ni], ah[mi], bl[ni]);
                mma_bf16(acc[mi][ni], al[mi], bh[ni]);
            }
    }
}

template <int NST, int COUTL, int ACT0, int ACT1, int ACT2, int ACT3>
__global__ void __launch_bounds__(128, 2)
fgemm_ms(const float* __restrict__ A1, const float* __restrict__ A2,
         const __nv_bfloat16* __restrict__ W0, const __nv_bfloat16* __restrict__ W1,
         const __nv_bfloat16* __restrict__ W2, const __nv_bfloat16* __restrict__ W3,
         const float* __restrict__ b0, const float* __restrict__ b1,
         const float* __restrict__ b2, const float* __restrict__ b3,
         float* __restrict__ out, int nrows, int ntiles) {
    constexpr int NFL = COUTL / 32;
    constexpr uint32_t AB  = 64 * 272;
    constexpr uint32_t WHB = 128 * 272;
    constexpr uint32_t WBYTES = 2 * WHB;
    constexpr int acts[4] = {ACT0, ACT1, ACT2, ACT3};

    const __nv_bfloat16* Wv[4] = {W0, W1, W2, W3};
    const float* bv[4] = {b0, b1, b2, b3};

    extern __shared__ char sm[];
    const uint32_t s0  = smem_u32(sm);
    const uint32_t sAh = s0, sAl = s0 + AB;
    const uint32_t sWh = s0 + 2 * AB, sWl = sWh + WHB;
    __shared__ __align__(8) unsigned long long bw_store;
    const uint32_t bw = smem_u32(&bw_store);

    const int tid  = threadIdx.x;
    const int lane = tid & 31;
    const int cw   = tid >> 5;
    const int g = lane >> 2, tq = lane & 3;
    const uint32_t aoff = (uint32_t)(lane & 15) * 272 + ((lane >> 4) ? 16 : 0);

    if (tid == 0) mbar_init(bw, 1);
    __syncthreads();
    if (tid == 0) { mbar_expect(bw, WBYTES); bulk_ld(sWh, W0, WBYTES, bw); }

    int ph = 0;
    for (int mt = blockIdx.x; mt < ntiles; mt += gridDim.x) {
        const int mbase = mt * 64;

        // ---- A tile: (A1 + A2) fp32 -> bf16 hi/lo --------------------------
        {
            const int row = tid >> 1, half = tid & 1;
            int grow = min(mbase + row, nrows - 1);
            const float* p1 = A1 + (size_t)grow * 128 + half * 64;
            const float* p2 = A2 + (size_t)grow * 128 + half * 64;
            const uint32_t d = row * 272 + half * 128;
#pragma unroll
            for (int i = 0; i < 8; i++) {
                float4 u0 = *(const float4*)(p1 + i * 8);
                float4 u1 = *(const float4*)(p1 + i * 8 + 4);
                float4 w0 = *(const float4*)(p2 + i * 8);
                float4 w1 = *(const float4*)(p2 + i * 8 + 4);
                float4 v0 = make_float4(u0.x + w0.x, u0.y + w0.y,
                                        u0.z + w0.z, u0.w + w0.w);
                float4 v1 = make_float4(u1.x + w1.x, u1.y + w1.y,
                                        u1.z + w1.z, u1.w + w1.w);
                uint32_t l0, l1, l2, l3;
                uint32_t h0 = split_hi2(v0.x, v0.y, l0);
                uint32_t h1 = split_hi2(v0.z, v0.w, l1);
                uint32_t h2 = split_hi2(v1.x, v1.y, l2);
                uint32_t h3 = split_hi2(v1.z, v1.w, l3);
                asm volatile("st.shared.v4.b32 [%0], {%1, %2, %3, %4};"
                             :: "r"(sAh + d + i * 16), "r"(h0), "r"(h1), "r"(h2), "r"(h3));
                asm volatile("st.shared.v4.b32 [%0], {%1, %2, %3, %4};"
                             :: "r"(sAl + d + i * 16), "r"(l0), "r"(l1), "r"(l2), "r"(l3));
            }
        }
        __syncthreads();

#pragma unroll
        for (int s = 0; s < NST; s++) {
            mbar_wait(bw, ph & 1); ph++;
            if (s < NST - 1) {
                float acc[4][4][4];
                mma_stage<4>(sAh, sAl, sWh, sWl, aoff, cw, lane, bv[s], acc);
                __syncthreads();                 // W + A/T reads done
                if (tid == 0) { mbar_expect(bw, WBYTES); bulk_ld(sWh, Wv[s + 1], WBYTES, bw); }
                // write T (act, bf16 split) over the A buffer
                const int act = acts[s];
#pragma unroll
                for (int mi = 0; mi < 4; mi++) {
                    const int r0 = mi * 16 + g;
#pragma unroll
                    for (int ni = 0; ni < 4; ni++) {
                        const int col = cw * 32 + ni * 8 + tq * 2;
                        float v0 = acc[mi][ni][0], v1 = acc[mi][ni][1];
                        float v2 = acc[mi][ni][2], v3 = acc[mi][ni][3];
                        if (act == 1) {
                            v0 = fmaxf(v0, 0.f); v1 = fmaxf(v1, 0.f);
                            v2 = fmaxf(v2, 0.f); v3 = fmaxf(v3, 0.f);
                        } else {
                            v0 = tanhf(v0); v1 = tanhf(v1);
                            v2 = tanhf(v2); v3 = tanhf(v3);
                        }
                        uint32_t lo0, lo1;
                        uint32_t hi0 = split_hi2(v0, v1, lo0);
                        uint32_t hi1 = split_hi2(v2, v3, lo1);
                        const uint32_t d0 = (uint32_t)r0 * 272 + col * 2;
                        asm volatile("st.shared.b32 [%0], %1;" :: "r"(sAh + d0), "r"(hi0));
                        asm volatile("st.shared.b32 [%0], %1;" :: "r"(sAl + d0), "r"(lo0));
                        asm volatile("st.shared.b32 [%0], %1;" :: "r"(sAh + d0 + 8 * 272), "r"(hi1));
                        asm volatile("st.shared.b32 [%0], %1;" :: "r"(sAl + d0 + 8 * 272), "r"(lo1));
                    }
                }
                __syncthreads();                 // T visible
            } else {
                float acc[4][NFL][4];
                mma_stage<NFL>(sAh, sAl, sWh, sWl, aoff, cw, lane, bv[s], acc);
                __syncthreads();                 // A/T + W reads done
                if (tid == 0 && mt + gridDim.x < ntiles) {
                    mbar_expect(bw, WBYTES); bulk_ld(sWh, W0, WBYTES, bw);
                }
                const int act = acts[s];
#pragma unroll
                for (int mi = 0; mi < 4; mi++) {
                    const int r0 = mbase + mi * 16 + g;
#pragma unroll
                    for (int ni = 0; ni < NFL; ni++) {
                        const int col = cw * (8 * NFL) + ni * 8 + tq * 2;
                        float v0 = acc[mi][ni][0], v1 = acc[mi][ni][1];
                        float v2 = acc[mi][ni][2], v3 = acc[mi][ni][3];
                        if (act == 2) {
                            v0 = tanhf(v0); v1 = tanhf(v1);
                            v2 = tanhf(v2); v3 = tanhf(v3);
                        }
                        if (r0 < nrows)
                            *(float2*)(out + (size_t)r0 * COUTL + col) = make_float2(v0, v1);
                        if (r0 + 8 < nrows)
                            *(float2*)(out + (size_t)(r0 + 8) * COUTL + col) = make_float2(v2, v3);
                    }
                }
            }
        }
    }
}

// ---------------- launch ------------------------------------------------------
extern "C" void kernel_launch(void* const* d_in, const int* in_sizes, int n_in,
                              void* d_out, int out_size) {
    const float* x    = (const float*)d_in[0];
    const int*   ei   = (const int*)d_in[1];
    const float* ef   = (const float*)d_in[2];
    const float* We1  = (const float*)d_in[3];
    const float* be1  = (const float*)d_in[4];
    const float* W1a  = (const float*)d_in[5];
    const float* b1a  = (const float*)d_in[6];
    const float* W1b  = (const float*)d_in[7];
    const float* b1b  = (const float*)d_in[8];
    const float* We2  = (const float*)d_in[9];
    const float* be2  = (const float*)d_in[10];
    const float* W2a  = (const float*)d_in[11];
    const float* b2a  = (const float*)d_in[12];
    const float* W2b  = (const float*)d_in[13];
    const float* b2b  = (const float*)d_in[14];
    const float* Wfc1 = (const float*)d_in[15];
    const float* bfc1 = (const float*)d_in[16];
    const float* Wfc2 = (const float*)d_in[17];
    const float* bfc2 = (const float*)d_in[18];
    float* out = (float*)d_out;

    float *agg, *h;
    __nv_bfloat16 *wb, *web;
    cudaGetSymbolAddress((void**)&agg, g_agg);
    cudaGetSymbolAddress((void**)&h,   g_h);
    cudaGetSymbolAddress((void**)&wb,  g_wb);
    cudaGetSymbolAddress((void**)&web, g_web);
    auto WB = [&](int m) { return wb + (size_t)m * 2 * 128 * 136; };
    auto WE = [&](int m, int s) { return web + ((size_t)m * 2 + s) * 128 * 40; };

    const int* srcp = ei;
    const int* dstp = ei + Ee;

    const int n4 = Nn * 128 / 4;
    const int zG = (n4 + 255) / 256;
    const int egG = (Ee + 127) / 128;            // 4688
    const int ntiles = (Nn + 63) / 64;           // 1563
    const int gG = 296;

    constexpr int SMF = 2 * 17408 + 2 * 34816;   // 104448
    auto k12 = fgemm_ms<2, 128, 1, 2, 0, 0>;
    auto k24 = fgemm_ms<4, 64, 1, 2, 2, 0>;
    cudaFuncSetAttribute(k12, cudaFuncAttributeMaxDynamicSharedMemorySize, SMF);
    cudaFuncSetAttribute(k24, cudaFuncAttributeMaxDynamicSharedMemorySize, SMF);

    prep_all<<<384, 256>>>(W1a, W1b, W2a, W2b, Wfc1, Wfc2, We1, We2, wb, web);

    // Layer 1: agg = 0; agg += relu-msgs; h = tanh(relu((agg + x)@W1a)@W1b)
    zero_kernel<<<zG, 256>>>((float4*)agg, n4);
    edge_kernel<<<egG, 256>>>(x, srcp, dstp, ef, WE(0, 0), WE(0, 1), be1, agg);
    k12<<<gG, 128, SMF>>>(agg, x, WB(0), WB(1), nullptr, nullptr,
                          b1a, b1b, nullptr, nullptr, h, Nn, ntiles);

    // Layer 2 + head fused: agg = 0; agg += msgs(h);
    // out = tanh(tanh(relu((agg + h)@W2a)@W2b)@Wfc1)@Wfc2 + biases
    zero_kernel<<<zG, 256>>>((float4*)agg, n4);
    edge_kernel<<<egG, 256>>>(h, srcp, dstp, ef, WE(1, 0), WE(1, 1), be2, agg);
    k24<<<gG, 128, SMF>>>(agg, h, WB(2), WB(3), WB(4), WB(5),
                          b2a, b2b, bfc1, bfc2, out, Nn, ntiles);
}

// round 11
// speedup vs baseline: 1.1087x; 1.1087x over previous
#include <cuda_runtime.h>
#include <cuda_bf16.h>
#include <cstdint>

#define Nn 100000
#define Ee 600000

// ---------------- scratch (allocation-free: __device__ globals) --------------
__device__ float g_agg[Nn * 128];
__device__ float g_h[Nn * 128];
__device__ __align__(16) __nv_bfloat16 g_wb[6][2][128 * 136];
__device__ __align__(16) __nv_bfloat16 g_web[2][2][128 * 40];

// ---------------- helpers -----------------------------------------------------
__device__ __forceinline__ void red_add_v4(float* p, float4 v) {
    asm volatile("red.global.add.v4.f32 [%0], {%1, %2, %3, %4};"
                 :: "l"(p), "f"(v.x), "f"(v.y), "f"(v.z), "f"(v.w)
                 : "memory");
}
__device__ __forceinline__ uint32_t smem_u32(const void* p) {
    return (uint32_t)__cvta_generic_to_shared(p);
}
__device__ __forceinline__ void cp_async16(uint32_t dst, const void* src) {
    asm volatile("cp.async.cg.shared.global [%0], [%1], 16;"
                 :: "r"(dst), "l"(src));
}
__device__ __forceinline__ void cp_commit() {
    asm volatile("cp.async.commit_group;");
}
__device__ __forceinline__ void cp_wait0() {
    asm volatile("cp.async.wait_group 0;" ::: "memory");
}
__device__ __forceinline__ void ldx4(uint32_t* r, uint32_t addr) {
    asm volatile("ldmatrix.sync.aligned.m8n8.x4.shared.b16 {%0, %1, %2, %3}, [%4];"
                 : "=r"(r[0]), "=r"(r[1]), "=r"(r[2]), "=r"(r[3]) : "r"(addr));
}
__device__ __forceinline__ void mma_bf16(float* c, const uint32_t* a,
                                         const uint32_t* b) {
    asm volatile("mma.sync.aligned.m16n8k16.row.col.f32.bf16.bf16.f32 "
                 "{%0, %1, %2, %3}, {%4, %5, %6, %7}, {%8, %9}, {%0, %1, %2, %3};"
                 : "+f"(c[0]), "+f"(c[1]), "+f"(c[2]), "+f"(c[3])
                 : "r"(a[0]), "r"(a[1]), "r"(a[2]), "r"(a[3]),
                   "r"(b[0]), "r"(b[1]));
}
__device__ __forceinline__ uint32_t bf2_u32(__nv_bfloat162 x) {
    uint32_t r;
    memcpy(&r, &x, 4);
    return r;
}
__device__ __forceinline__ uint32_t split_hi2(float a, float b, uint32_t& lo) {
    __nv_bfloat162 h = __floats2bfloat162_rn(a, b);
    __nv_bfloat162 l = __floats2bfloat162_rn(a - __bfloat162float(h.x),
                                             b - __bfloat162float(h.y));
    lo = bf2_u32(l);
    return bf2_u32(h);
}
// ---- bulk copy + mbarrier ----
__device__ __forceinline__ void mbar_init(uint32_t mb, uint32_t cnt) {
    asm volatile("mbarrier.init.shared.b64 [%0], %1;" :: "r"(mb), "r"(cnt) : "memory");
}
__device__ __forceinline__ void mbar_expect(uint32_t mb, uint32_t bytes) {
    asm volatile("mbarrier.arrive.expect_tx.shared.b64 _, [%0], %1;"
                 :: "r"(mb), "r"(bytes) : "memory");
}
__device__ __forceinline__ void bulk_ld(uint32_t dst, const void* src,
                                        uint32_t bytes, uint32_t mb) {
    asm volatile("cp.async.bulk.shared::cta.global.mbarrier::complete_tx::bytes "
                 "[%0], [%1], %2, [%3];"
                 :: "r"(dst), "l"(src), "r"(bytes), "r"(mb) : "memory");
}
__device__ __forceinline__ void mbar_wait(uint32_t mb, uint32_t parity) {
    uint32_t done;
    asm volatile("{\n\t.reg .pred p;\n\t"
                 "mbarrier.try_wait.parity.acquire.cta.shared::cta.b64 p, [%1], %2;\n\t"
                 "selp.b32 %0, 1, 0, p;\n\t}"
                 : "=r"(done) : "r"(mb), "r"(parity) : "memory");
    if (!done) {
        asm volatile("{\n\t.reg .pred P1;\n\t"
                     "WL_%=:\n\t"
                     "mbarrier.try_wait.parity.acquire.cta.shared::cta.b64 P1, [%0], %1, 0x989680;\n\t"
                     "@P1 bra.uni WD_%=;\n\t"
                     "bra.uni WL_%=;\n\t"
                     "WD_%=:\n\t}"
                     :: "r"(mb), "r"(parity) : "memory");
    }
}

// ---------------- init copy ---------------------------------------------------
__global__ void __launch_bounds__(256) copy_kernel(float4* __restrict__ dst,
                                                   const float4* __restrict__ src,
                                                   int n4) {
    int i = blockIdx.x * blockDim.x + threadIdx.x;
    if (i < n4) dst[i] = src[i];
}

// ---------------- fused weight prep (one launch) -------------------------------
__global__ void __launch_bounds__(256)
prep_all(const float* __restrict__ W1a, const float* __restrict__ W1b,
         const float* __restrict__ W2a, const float* __restrict__ W2b,
         const float* __restrict__ Wfc1, const float* __restrict__ Wfc2,
         const float* __restrict__ We1, const float* __restrict__ We2,
         __nv_bfloat16* __restrict__ wb, __nv_bfloat16* __restrict__ web) {
    int id = blockIdx.x * 256 + threadIdx.x;
    if (id < 81920) {
        int m = id / 16384, e = id % 16384;
        const float* W = (m == 0) ? W1a : (m == 1) ? W1b
                       : (m == 2) ? W2a : (m == 3) ? W2b : Wfc1;
        int n = e >> 7, k = e & 127;
        float v = W[k * 128 + n];
        __nv_bfloat16 h = __float2bfloat16_rn(v);
        __nv_bfloat16 l = __float2bfloat16_rn(v - __bfloat162float(h));
        wb[(size_t)m * 2 * 128 * 136 + n * 136 + k] = h;
        wb[((size_t)m * 2 + 1) * 128 * 136 + n * 136 + k] = l;
    } else if (id < 90112) {
        int e = id - 81920;
        int n = e >> 7, k = e & 127;
        float v = Wfc2[k * 64 + n];
        __nv_bfloat16 h = __float2bfloat16_rn(v);
        __nv_bfloat16 l = __float2bfloat16_rn(v - __bfloat162float(h));
        wb[(size_t)5 * 2 * 128 * 136 + n * 136 + k] = h;
        wb[((size_t)5 * 2 + 1) * 128 * 136 + n * 136 + k] = l;
    } else if (id < 98304) {
        int e = id - 90112;
        int m = e >> 12; e &= 4095;
        int n = e >> 5, k = e & 31;
        const float* We = m ? We2 : We1;
        float v = We[k * 128 + n];
        __nv_bfloat16 h = __float2bfloat16_rn(v);
        __nv_bfloat16 l = __float2bfloat16_rn(v - __bfloat162float(h));
        web[(size_t)m * 2 * 128 * 40 + n * 40 + k] = h;
        web[((size_t)m * 2 + 1) * 128 * 40 + n * 40 + k] = l;
    }
}

// ---------------- HMMA fused edge kernel (R8 MMA + shuffle-merged epilogue) ---
__global__ void __launch_bounds__(256, 2)
edge_kernel(const float* __restrict__ xin,
            const int* __restrict__ src, const int* __restrict__ dst,
            const float* __restrict__ ef,
            const __nv_bfloat16* __restrict__ Weh,
            const __nv_bfloat16* __restrict__ Wel,
            const float* __restrict__ be,
            float* __restrict__ agg) {
    __shared__ __align__(16) __nv_bfloat16 sWeh[128 * 40], sWel[128 * 40];
    __shared__ __align__(16) __nv_bfloat16 sEfh[128 * 40], sEfl[128 * 40];
    __shared__ float sbias[128];
    __shared__ int ssrc[128], sdst[128];

    const int tid  = threadIdx.x;
    const int wid  = tid >> 5;
    const int lane = tid & 31;
    const int base = blockIdx.x * 128;
    const int nvalid = min(128, Ee - base);

    const uint32_t swh = smem_u32(sWeh), swl = smem_u32(sWel);
    for (int i = tid; i < 640; i += 256) {
        cp_async16(swh + i * 16, (const char*)Weh + i * 16);
        cp_async16(swl + i * 16, (const char*)Wel + i * 16);
    }
    cp_commit();

    if (tid < 128) {
        sbias[tid] = be[tid];
        int e = min(base + tid, Ee - 1);
        ssrc[tid] = src[e];
        sdst[tid] = dst[e];
    }

    {
        const int edge = tid >> 1, half = tid & 1;
        int ge = min(base + edge, Ee - 1);
        const float4* ap = (const float4*)(ef + (size_t)ge * 32 + half * 16);
        const uint32_t dh = smem_u32(sEfh) + edge * 80 + half * 32;
        const uint32_t dl = smem_u32(sEfl) + edge * 80 + half * 32;
#pragma unroll
        for (int i = 0; i < 4; i++) {
            float4 v = ap[i];
            uint32_t l0, l1;
            uint32_t h0 = split_hi2(v.x, v.y, l0);
            uint32_t h1 = split_hi2(v.z, v.w, l1);
            asm volatile("st.shared.v2.b32 [%0], {%1, %2};"
                         :: "r"(dh + i * 8), "r"(h0), "r"(h1));
            asm volatile("st.shared.v2.b32 [%0], {%1, %2};"
                         :: "r"(dl + i * 8), "r"(l0), "r"(l1));
        }
    }
    cp_wait0();
    __syncthreads();

    const int g = lane >> 2, tq = lane & 3;
    const uint32_t aoff = smem_u32(sEfh)
        + (uint32_t)(wid * 16 + (lane & 15)) * 80 + ((lane >> 4) ? 16 : 0);
    const uint32_t aloff = aoff + (smem_u32(sEfl) - smem_u32(sEfh));
    const int brow = (lane & 7) + ((lane >> 4) << 3);
    const uint32_t boff = smem_u32(sWeh) + (uint32_t)brow * 80 + ((lane & 8) ? 16 : 0);
    const uint32_t bloff = boff + (smem_u32(sWel) - smem_u32(sWeh));

    float acc[16][4];
#pragma unroll
    for (int ni = 0; ni < 16; ni++) {
        float2 b = *(const float2*)(sbias + ni * 8 + tq * 2);
        acc[ni][0] = b.x; acc[ni][1] = b.y;
        acc[ni][2] = b.x; acc[ni][3] = b.y;
    }

#pragma unroll
    for (int ks = 0; ks < 2; ks++) {
        uint32_t ah[4], al[4];
        ldx4(ah, aoff + ks * 32);
        ldx4(al, aloff + ks * 32);
#pragma unroll
        for (int np = 0; np < 8; np++) {
            uint32_t rh[4], rl[4];
            ldx4(rh, boff + np * (16 * 80) + ks * 32);
            ldx4(rl, bloff + np * (16 * 80) + ks * 32);
            uint32_t bh0[2] = {rh[0], rh[1]}, bh1[2] = {rh[2], rh[3]};
            uint32_t bl0[2] = {rl[0], rl[1]}, bl1[2] = {rl[2], rl[3]};
            mma_bf16(acc[np * 2],     ah, bh0);
            mma_bf16(acc[np * 2],     ah, bl0);
            mma_bf16(acc[np * 2],     al, bh0);
            mma_bf16(acc[np * 2 + 1], ah, bh1);
            mma_bf16(acc[np * 2 + 1], ah, bl1);
            mma_bf16(acc[np * 2 + 1], al, bh1);
        }
    }

    // ---- lane-pair merge: adjacent lanes (tq=2j,2j+1) swap halves so each
    // thread owns float4 col-quads for 8 ni-groups (even lanes ni 0..7,
    // odd lanes ni 8..15). All constant register indices (selects, no spills).
    const bool evn = ((lane & 1) == 0);
    float4 rowA[8], rowB[8];
#pragma unroll
    for (int i = 0; i < 8; i++) {
        float s0 = evn ? acc[i + 8][0] : acc[i][0];
        float s1 = evn ? acc[i + 8][1] : acc[i][1];
        float s2 = evn ? acc[i + 8][2] : acc[i][2];
        float s3 = evn ? acc[i + 8][3] : acc[i][3];
        float g0 = __shfl_xor_sync(0xffffffffu, s0, 1);
        float g1 = __shfl_xor_sync(0xffffffffu, s1, 1);
        float g2 = __shfl_xor_sync(0xffffffffu, s2, 1);
        float g3 = __shfl_xor_sync(0xffffffffu, s3, 1);
        float k0 = evn ? acc[i][0] : acc[i + 8][0];
        float k1 = evn ? acc[i][1] : acc[i + 8][1];
        float k2 = evn ? acc[i][2] : acc[i + 8][2];
        float k3 = evn ? acc[i][3] : acc[i + 8][3];
        rowA[i] = evn ? make_float4(k0, k1, g0, g1) : make_float4(g0, g1, k0, k1);
        rowB[i] = evn ? make_float4(k2, k3, g2, g3) : make_float4(g2, g3, k2, k3);
    }
    const int nk0 = evn ? 0 : 8;
    const int jq  = (lane >> 1) & 1;

    const int er0 = wid * 16 + g;
#pragma unroll
    for (int half = 0; half < 2; half++) {
        const int er = er0 + half * 8;
        if (er < nvalid) {
            const size_t srow = (size_t)ssrc[er] * 128;
            const size_t drow = (size_t)sdst[er] * 128;
#pragma unroll
            for (int i = 0; i < 8; i++) {
                const int cb = (nk0 + i) * 8 + 4 * jq;
                float4 ev = half ? rowB[i] : rowA[i];
                float4 xv = *(const float4*)(xin + srow + cb);
                float4 m;
                m.x = fmaxf(xv.x + ev.x, 0.f);
                m.y = fmaxf(xv.y + ev.y, 0.f);
                m.z = fmaxf(xv.z + ev.z, 0.f);
                m.w = fmaxf(xv.w + ev.w, 0.f);
                red_add_v4(agg + drow + cb, m);
            }
        }
    }
}

// ---------------- shared GEMM pieces -------------------------------------------
template <int NF>
__device__ __forceinline__ void mma_stage(
    uint32_t sAh, uint32_t sAl, uint32_t sWh, uint32_t sWl,
    uint32_t aoff, int cw, int lane, const float* __restrict__ bias,
    float (&acc)[4][NF][4]) {
    const int tq = lane & 3;
    const int brow = (lane & 7) + ((lane >> 4) << 3);
    const uint32_t boff = (uint32_t)(cw * (8 * NF) + brow) * 272
                        + ((lane & 8) ? 16 : 0);
#pragma unroll
    for (int ni = 0; ni < NF; ni++) {
        float2 b = __ldg((const float2*)(bias + cw * (8 * NF) + ni * 8 + tq * 2));
#pragma unroll
        for (int mi = 0; mi < 4; mi++) {
            acc[mi][ni][0] = b.x; acc[mi][ni][1] = b.y;
            acc[mi][ni][2] = b.x; acc[mi][ni][3] = b.y;
        }
    }
#pragma unroll
    for (int ks = 0; ks < 8; ks++) {
        uint32_t ah[4][4], al[4][4], bh[NF][2], bl[NF][2];
#pragma unroll
        for (int mi = 0; mi < 4; mi++) {
            ldx4(ah[mi], sAh + aoff + mi * 4352 + ks * 32);
            ldx4(al[mi], sAl + aoff + mi * 4352 + ks * 32);
        }
#pragma unroll
        for (int np = 0; np < NF / 2; np++) {
            uint32_t r[4];
            ldx4(r, sWh + boff + np * 4352 + ks * 32);
            bh[np * 2][0] = r[0]; bh[np * 2][1] = r[1];
            bh[np * 2 + 1][0] = r[2]; bh[np * 2 + 1][1] = r[3];
            ldx4(r, sWl + boff + np * 4352 + ks * 32);
            bl[np * 2][0] = r[0]; bl[np * 2][1] = r[1];
            bl[np * 2 + 1][0] = r[2]; bl[np * 2 + 1][1] = r[3];
        }
#pragma unroll
        for (int mi = 0; mi < 4; mi++)
#pragma unroll
            for (int ni = 0; ni < NF; ni++) {
                mma_bf16(acc[mi][ni], ah[mi], bh[ni]);
                mma_bf16(acc[mi][ni], ah[mi], bl[ni]);
                mma_bf16(acc[mi][ni], al[mi], bh[ni]);
            }
    }
}

// write T (act + bf16 split) over the A smem buffer (128-col stage)
template <int ACT>
__device__ __forceinline__ void twrite(
    float (&acc)[4][4][4], uint32_t sAh, uint32_t sAl, int cw, int lane) {
    const int g = lane >> 2, tq = lane & 3;
#pragma unroll
    for (int mi = 0; mi < 4; mi++) {
        const int r0 = mi * 16 + g;
#pragma unroll
        for (int ni = 0; ni < 4; ni++) {
            const int col = cw * 32 + ni * 8 + tq * 2;
            float v0 = acc[mi][ni][0], v1 = acc[mi][ni][1];
            float v2 = acc[mi][ni][2], v3 = acc[mi][ni][3];
            if (ACT == 1) {
                v0 = fmaxf(v0, 0.f); v1 = fmaxf(v1, 0.f);
                v2 = fmaxf(v2, 0.f); v3 = fmaxf(v3, 0.f);
            } else {
                v0 = tanhf(v0); v1 = tanhf(v1);
                v2 = tanhf(v2); v3 = tanhf(v3);
            }
            uint32_t lo0, lo1;
            uint32_t hi0 = split_hi2(v0, v1, lo0);
            uint32_t hi1 = split_hi2(v2, v3, lo1);
            const uint32_t d0 = (uint32_t)r0 * 272 + col * 2;
            asm volatile("st.shared.b32 [%0], %1;" :: "r"(sAh + d0), "r"(hi0));
            asm volatile("st.shared.b32 [%0], %1;" :: "r"(sAl + d0), "r"(lo0));
            asm volatile("st.shared.b32 [%0], %1;" :: "r"(sAh + d0 + 8 * 272), "r"(hi1));
            asm volatile("st.shared.b32 [%0], %1;" :: "r"(sAl + d0 + 8 * 272), "r"(lo1));
        }
    }
}

// A-convert: 64x128 fp32 tile -> bf16 hi/lo smem (pitch 136)
__device__ __forceinline__ void aconvert(
    const float* __restrict__ A, int mbase, int nrows,
    uint32_t sAh, uint32_t sAl, int tid) {
    const int row = tid >> 1, half = tid & 1;
    int grow = min(mbase + row, nrows - 1);
    const float* ap = A + (size_t)grow * 128 + half * 64;
    const uint32_t d = row * 272 + half * 128;
#pragma unroll
    for (int i = 0; i < 8; i++) {
        float4 v0 = *(const float4*)(ap + i * 8);
        float4 v1 = *(const float4*)(ap + i * 8 + 4);
        uint32_t l0, l1, l2, l3;
        uint32_t h0 = split_hi2(v0.x, v0.y, l0);
        uint32_t h1 = split_hi2(v0.z, v0.w, l1);
        uint32_t h2 = split_hi2(v1.x, v1.y, l2);
        uint32_t h3 = split_hi2(v1.z, v1.w, l3);
        asm volatile("st.shared.v4.b32 [%0], {%1, %2, %3, %4};"
                     :: "r"(sAh + d + i * 16), "r"(h0), "r"(h1), "r"(h2), "r"(h3));
        asm volatile("st.shared.v4.b32 [%0], {%1, %2, %3, %4};"
                     :: "r"(sAl + d + i * 16), "r"(l0), "r"(l1), "r"(l2), "r"(l3));
    }
}

// ---------------- two-stage fused node GEMM (R8 exact, refactored) -------------
template <int COUT2, int ACT1, int ACT2>
__global__ void __launch_bounds__(128, 2)
fgemm(const float* __restrict__ A,
      const __nv_bfloat16* __restrict__ W1, const __nv_bfloat16* __restrict__ W2,
      const float* __restrict__ b1, const float* __restrict__ b2,
      float* __restrict__ out, float* __restrict__ out2, int nrows, int ntiles) {
    constexpr int NW2 = COUT2 / 4;
    constexpr int NF2 = NW2 / 8;
    constexpr uint32_t AB  = 64 * 272;
    constexpr uint32_t WHB = 128 * 272;
    constexpr uint32_t WBYTES = 2 * WHB;

    extern __shared__ char sm[];
    const uint32_t s0  = smem_u32(sm);
    const uint32_t sAh = s0, sAl = s0 + AB;
    const uint32_t sWh = s0 + 2 * AB, sWl = sWh + WHB;
    __shared__ __align__(8) unsigned long long bw_store;
    const uint32_t bw = smem_u32(&bw_store);

    const int tid  = threadIdx.x;
    const int lane = tid & 31;
    const int cw   = tid >> 5;
    const int g = lane >> 2, tq = lane & 3;
    const uint32_t aoff = (uint32_t)(lane & 15) * 272 + ((lane >> 4) ? 16 : 0);

    if (tid == 0) mbar_init(bw, 1);
    __syncthreads();
    if (tid == 0) { mbar_expect(bw, WBYTES); bulk_ld(sWh, W1, WBYTES, bw); }

    int ph = 0;
    for (int mt = blockIdx.x; mt < ntiles; mt += gridDim.x) {
        const int mbase = mt * 64;
        aconvert(A, mbase, nrows, sAh, sAl, tid);
        __syncthreads();
        mbar_wait(bw, ph & 1); ph++;

        float acc[4][4][4];
        mma_stage<4>(sAh, sAl, sWh, sWl, aoff, cw, lane, b1, acc);
        __syncthreads();
        if (tid == 0) { mbar_expect(bw, WBYTES); bulk_ld(sWh, W2, WBYTES, bw); }
        twrite<ACT1>(acc, sAh, sAl, cw, lane);
        __syncthreads();
        mbar_wait(bw, ph & 1); ph++;

        float acc2[4][NF2][4];
        mma_stage<NF2>(sAh, sAl, sWh, sWl, aoff, cw, lane, b2, acc2);
        __syncthreads();
        if (tid == 0 && mt + gridDim.x < ntiles) {
            mbar_expect(bw, WBYTES); bulk_ld(sWh, W1, WBYTES, bw);
        }
#pragma unroll
        for (int mi = 0; mi < 4; mi++) {
            const int r0 = mbase + mi * 16 + g;
#pragma unroll
            for (int ni = 0; ni < NF2; ni++) {
                const int col = cw * NW2 + ni * 8 + tq * 2;
                float v0 = acc2[mi][ni][0], v1 = acc2[mi][ni][1];
                float v2 = acc2[mi][ni][2], v3 = acc2[mi][ni][3];
                if (ACT2 == 2) {
                    v0 = tanhf(v0); v1 = tanhf(v1);
                    v2 = tanhf(v2); v3 = tanhf(v3);
                }
                if (r0 < nrows) {
                    *(float2*)(out + (size_t)r0 * COUT2 + col) = make_float2(v0, v1);
                    if (out2)
                        *(float2*)(out2 + (size_t)r0 * COUT2 + col) = make_float2(v0, v1);
                }
                if (r0 + 8 < nrows) {
                    *(float2*)(out + (size_t)(r0 + 8) * COUT2 + col) = make_float2(v2, v3);
                    if (out2)
                        *(float2*)(out2 + (size_t)(r0 + 8) * COUT2 + col) = make_float2(v2, v3);
                }
            }
        }
    }
}

// ---------------- four-stage fused GEMM: layer2 MLP + head ---------------------
// out = (tanh(tanh(relu(A@Wa+ba)@Wb+bb)@Wc+bc))@Wd + bd, straight-line stages.
__global__ void __launch_bounds__(128, 2)
fgemm4(const float* __restrict__ A,
       const __nv_bfloat16* __restrict__ Wa, const __nv_bfloat16* __restrict__ Wb,
       const __nv_bfloat16* __restrict__ Wc, const __nv_bfloat16* __restrict__ Wd,
       const float* __restrict__ ba, const float* __restrict__ bb,
       const float* __restrict__ bc, const float* __restrict__ bd,
       float* __restrict__ out, int nrows, int ntiles) {
    constexpr uint32_t AB  = 64 * 272;
    constexpr uint32_t WHB = 128 * 272;
    constexpr uint32_t WBYTES = 2 * WHB;

    extern __shared__ char sm[];
    const uint32_t s0  = smem_u32(sm);
    const uint32_t sAh = s0, sAl = s0 + AB;
    const uint32_t sWh = s0 + 2 * AB, sWl = sWh + WHB;
    __shared__ __align__(8) unsigned long long bw_store;
    const uint32_t bw = smem_u32(&bw_store);

    const int tid  = threadIdx.x;
    const int lane = tid & 31;
    const int cw   = tid >> 5;
    const int g = lane >> 2, tq = lane & 3;
    const uint32_t aoff = (uint32_t)(lane & 15) * 272 + ((lane >> 4) ? 16 : 0);

    if (tid == 0) mbar_init(bw, 1);
    __syncthreads();
    if (tid == 0) { mbar_expect(bw, WBYTES); bulk_ld(sWh, Wa, WBYTES, bw); }

    int ph = 0;
    for (int mt = blockIdx.x; mt < ntiles; mt += gridDim.x) {
        const int mbase = mt * 64;
        aconvert(A, mbase, nrows, sAh, sAl, tid);
        __syncthreads();
        mbar_wait(bw, ph & 1); ph++;

        // stage 1: relu(A@Wa+ba)
        {
            float acc[4][4][4];
            mma_stage<4>(sAh, sAl, sWh, sWl, aoff, cw, lane, ba, acc);
            __syncthreads();
            if (tid == 0) { mbar_expect(bw, WBYTES); bulk_ld(sWh, Wb, WBYTES, bw); }
            twrite<1>(acc, sAh, sAl, cw, lane);
            __syncthreads();
            mbar_wait(bw, ph & 1); ph++;
        }
        // stage 2: tanh(T@Wb+bb)
        {
            float acc[4][4][4];
            mma_stage<4>(sAh, sAl, sWh, sWl, aoff, cw, lane, bb, acc);
            __syncthreads();
            if (tid == 0) { mbar_expect(bw, WBYTES); bulk_ld(sWh, Wc, WBYTES, bw); }
            twrite<2>(acc, sAh, sAl, cw, lane);
            __syncthreads();
            mbar_wait(bw, ph & 1); ph++;
        }
        // stage 3: tanh(T@Wc+bc)
        {
            float acc[4][4][4];
            mma_stage<4>(sAh, sAl, sWh, sWl, aoff, cw, lane, bc, acc);
            __syncthreads();
            if (tid == 0) { mbar_expect(bw, WBYTES); bulk_ld(sWh, Wd, WBYTES, bw); }
            twrite<2>(acc, sAh, sAl, cw, lane);
            __syncthreads();
            mbar_wait(bw, ph & 1); ph++;
        }
        // stage 4: T@Wd+bd -> out (COUT 64)
        {
            float acc[4][2][4];
            mma_stage<2>(sAh, sAl, sWh, sWl, aoff, cw, lane, bd, acc);
            __syncthreads();
            if (tid == 0 && mt + gridDim.x < ntiles) {
                mbar_expect(bw, WBYTES); bulk_ld(sWh, Wa, WBYTES, bw);
            }
#pragma unroll
            for (int mi = 0; mi < 4; mi++) {
                const int r0 = mbase + mi * 16 + g;
#pragma unroll
                for (int ni = 0; ni < 2; ni++) {
                    const int col = cw * 16 + ni * 8 + tq * 2;
                    if (r0 < nrows)
                        *(float2*)(out + (size_t)r0 * 64 + col)
                            = make_float2(acc[mi][ni][0], acc[mi][ni][1]);
                    if (r0 + 8 < nrows)
                        *(float2*)(out + (size_t)(r0 + 8) * 64 + col)
                            = make_float2(acc[mi][ni][2], acc[mi][ni][3]);
                }
            }
        }
    }
}

// ---------------- launch ------------------------------------------------------
extern "C" void kernel_launch(void* const* d_in, const int* in_sizes, int n_in,
                              void* d_out, int out_size) {
    const float* x    = (const float*)d_in[0];
    const int*   ei   = (const int*)d_in[1];
    const float* ef   = (const float*)d_in[2];
    const float* We1  = (const float*)d_in[3];
    const float* be1  = (const float*)d_in[4];
    const float* W1a  = (const float*)d_in[5];
    const float* b1a  = (const float*)d_in[6];
    const float* W1b  = (const float*)d_in[7];
    const float* b1b  = (const float*)d_in[8];
    const float* We2  = (const float*)d_in[9];
    const float* be2  = (const float*)d_in[10];
    const float* W2a  = (const float*)d_in[11];
    const float* b2a  = (const float*)d_in[12];
    const float* W2b  = (const float*)d_in[13];
    const float* b2b  = (const float*)d_in[14];
    const float* Wfc1 = (const float*)d_in[15];
    const float* bfc1 = (const float*)d_in[16];
    const float* Wfc2 = (const float*)d_in[17];
    const float* bfc2 = (const float*)d_in[18];
    float* out = (float*)d_out;

    float *agg, *h;
    __nv_bfloat16 *wb, *web;
    cudaGetSymbolAddress((void**)&agg, g_agg);
    cudaGetSymbolAddress((void**)&h,   g_h);
    cudaGetSymbolAddress((void**)&wb,  g_wb);
    cudaGetSymbolAddress((void**)&web, g_web);
    auto WB = [&](int m) { return wb + (size_t)m * 2 * 128 * 136; };
    auto WE = [&](int m, int s) { return web + ((size_t)m * 2 + s) * 128 * 40; };

    const int* srcp = ei;
    const int* dstp = ei + Ee;

    const int n4 = Nn * 128 / 4;
    const int cpG = (n4 + 255) / 256;
    const int egG = (Ee + 127) / 128;            // 4688
    const int ntiles = (Nn + 63) / 64;           // 1563
    const int gG = 296;

    constexpr int SMF = 2 * 17408 + 2 * 34816;   // 104448
    cudaFuncSetAttribute(fgemm<128, 1, 2>, cudaFuncAttributeMaxDynamicSharedMemorySize, SMF);
    cudaFuncSetAttribute(fgemm4, cudaFuncAttributeMaxDynamicSharedMemorySize, SMF);

    prep_all<<<384, 256>>>(W1a, W1b, W2a, W2b, Wfc1, Wfc2, We1, We2, wb, web);

    // Layer 1: agg = x; agg += relu-msgs; h = tanh(relu(agg@W1a)@W1b); agg = h
    copy_kernel<<<cpG, 256>>>((float4*)agg, (const float4*)x, n4);
    edge_kernel<<<egG, 256>>>(x, srcp, dstp, ef, WE(0, 0), WE(0, 1), be1, agg);
    fgemm<128, 1, 2><<<gG, 128, SMF>>>(agg, WB(0), WB(1), b1a, b1b, h, agg, Nn, ntiles);

    // Layer 2 + head (fused): agg(=h) += msgs(h);
    // out = tanh(tanh(relu(agg@W2a)@W2b)@Wfc1)@Wfc2
    edge_kernel<<<egG, 256>>>(h, srcp, dstp, ef, WE(1, 0), WE(1, 1), be2, agg);
    fgemm4<<<gG, 128, SMF>>>(agg, WB(2), WB(3), WB(4), WB(5),
                             b2a, b2b, bfc1, bfc2, out, Nn, ntiles);
}